// round 16
// baseline (speedup 1.0000x reference)
#include <cuda_runtime.h>
#include <cuda_fp16.h>
#include <cstdint>
#include <math.h>

// Problem dims (fixed by the dataset)
#define NTOK   8192            // B*S = 4*2048
#define HD     1024
#define FD     4096
#define NE     8
#define NPAIR  (NTOK * 2)      // top-2

// ---------------- scratch (__device__ globals: allocation-rule safe) --------
__device__ int    g_count[NE];
__device__ int    g_list[NE][NTOK];           // pair ids (t*2+k) per expert
__device__ float  g_pairw[NPAIR];             // gate prob per pair slot
__device__ __half g_w1h[(size_t)NE * HD * FD];   // 67 MB  [e][H][F]
__device__ __half g_w2h[(size_t)NE * FD * HD];   // 67 MB  [e][F][H]
__device__ __half g_xh[(size_t)NTOK * HD];       // 16 MB
__device__ __half g_hh[(size_t)NPAIR * FD];      // 134 MB fp16 intermediate

__device__ __forceinline__ uint2 cvt4(float4 v) {
    uint2 o;
    *reinterpret_cast<__half2*>(&o.x) = __floats2half2_rn(v.x, v.y);
    *reinterpret_cast<__half2*>(&o.y) = __floats2half2_rn(v.z, v.w);
    return o;
}

// ---------------- zero the expert counters (must precede gate atomics) ------
__global__ void zero_ctr() {
    if (threadIdx.x < NE) g_count[threadIdx.x] = 0;
}

// ---------------- gating + x fp16 convert + w1 convert (fused) --------------
__global__ void gate_kernel(const float* __restrict__ x,
                            const float* __restrict__ gw,
                            const float4* __restrict__ w1f) {
    const int t = blockIdx.x;
    const int warp = threadIdx.x >> 5, lane = threadIdx.x & 31;
    const int tid = threadIdx.x;
    __shared__ float logits[NE];
    const float* xr = x + (size_t)t * HD;
    {   // fused x -> fp16 (row is cache-hot)
        float4 v = *reinterpret_cast<const float4*>(xr + tid * 4);
        reinterpret_cast<uint2*>(g_xh + (size_t)t * HD)[tid] = cvt4(v);
    }
    {   // fused w1 -> fp16: 8192 blocks x 1024 float4 = full w1
        uint2* dst = (uint2*)g_w1h;
        const size_t base = (size_t)t * 1024 + tid;
#pragma unroll
        for (int k = 0; k < 4; ++k) dst[base + k * 256] = cvt4(w1f[base + k * 256]);
    }
    const float* wr = gw + warp * HD;       // 8 warps = 8 experts
    float s = 0.f;
#pragma unroll 8
    for (int h = lane; h < HD; h += 32) s = fmaf(xr[h], wr[h], s);
#pragma unroll
    for (int o = 16; o > 0; o >>= 1) s += __shfl_xor_sync(0xffffffffu, s, o);
    if (lane == 0) logits[warp] = s;
    __syncthreads();
    if (threadIdx.x == 0) {
        float mx = logits[0];
        for (int e = 1; e < NE; e++) mx = fmaxf(mx, logits[e]);
        float pe[NE]; float den = 0.f;
        for (int e = 0; e < NE; e++) { pe[e] = expf(logits[e] - mx); den += pe[e]; }
        int i1 = 0;
        for (int e = 1; e < NE; e++) if (pe[e] > pe[i1]) i1 = e;  // lowest idx on tie
        int i2 = (i1 == 0) ? 1 : 0;
        for (int e = 0; e < NE; e++) if (e != i1 && pe[e] > pe[i2]) i2 = e;
        float inv = 1.f / den;
        int p0 = t * 2, p1 = t * 2 + 1;
        g_pairw[p0] = pe[i1] * inv;
        g_pairw[p1] = pe[i2] * inv;
        int k0 = atomicAdd(&g_count[i1], 1); g_list[i1][k0] = p0;
        int k1 = atomicAdd(&g_count[i2], 1); g_list[i2][k1] = p1;
    }
}

// ---------------- mma / ldmatrix helpers ------------------------------------
__device__ __forceinline__ void mma_f16(float c[4], const uint32_t a[4],
                                        uint32_t b0, uint32_t b1) {
    asm volatile(
        "mma.sync.aligned.m16n8k16.row.col.f32.f16.f16.f32 "
        "{%0,%1,%2,%3},{%4,%5,%6,%7},{%8,%9},{%0,%1,%2,%3};\n"
        : "+f"(c[0]), "+f"(c[1]), "+f"(c[2]), "+f"(c[3])
        : "r"(a[0]), "r"(a[1]), "r"(a[2]), "r"(a[3]), "r"(b0), "r"(b1));
}
__device__ __forceinline__ void ldsm_x4(uint32_t r[4], uint32_t a) {
    asm volatile("ldmatrix.sync.aligned.m8n8.x4.shared.b16 {%0,%1,%2,%3},[%4];\n"
                 : "=r"(r[0]), "=r"(r[1]), "=r"(r[2]), "=r"(r[3]) : "r"(a));
}
__device__ __forceinline__ void ldsm_x4_t(uint32_t r[4], uint32_t a) {
    asm volatile("ldmatrix.sync.aligned.m8n8.x4.trans.shared.b16 {%0,%1,%2,%3},[%4];\n"
                 : "=r"(r[0]), "=r"(r[1]), "=r"(r[2]), "=r"(r[3]) : "r"(a));
}
__device__ __forceinline__ void cp16(uint32_t dst, const void* src) {
    asm volatile("cp.async.cg.shared.global [%0], [%1], 16;\n" :: "r"(dst), "l"(src));
}
__device__ __forceinline__ void redv4(float* a, float v0, float v1, float v2, float v3) {
    asm volatile("red.global.add.v4.f32 [%0], {%1,%2,%3,%4};"
                 :: "l"(a), "f"(v0), "f"(v1), "f"(v2), "f"(v3) : "memory");
}

// ---------------- grouped gather-GEMM (fp16 in, fp32 acc) -------------------
// CTA tile 128x256, 512 threads = 16 warps (2x8) of 64x32 each (acc=64 regs,
// ~122 regs/thread -> 1 CTA/SM, 4 warps/SMSP). BK=64, 3-stage pipeline,
// R12 mainloop body. Wider B tile halves per-SMSP LDGSTS traffic.
#define GT 512
#define BM 128
#define BN 256
#define BK 64
#define STAGES 3
#define AS 72                  // A row stride in halves (144B, 16B-aligned)
#define BS2 264                // B row stride in halves (528B, 16B-aligned)
#define A_BYTES (BM * AS * 2)              // 18432
#define STAGE_B (A_BYTES + BK * BS2 * 2)   // 18432 + 33792 = 52224

template <int MODE>
__global__ __launch_bounds__(GT, 1)
void moe_gemm(const float* __restrict__ b1g, const float* __restrict__ b2g,
              const float4* __restrict__ w2f, float* __restrict__ out) {
    constexpr int K = (MODE == 0) ? HD : FD;
    constexpr int N = (MODE == 0) ? FD : HD;
    constexpr int KT = K / BK;
    const int tid = threadIdx.x;
    const int e = blockIdx.z;
    const int cnt = g_count[e];
    const int rowBase = blockIdx.y * BM;
    const bool active = rowBase < cnt;          // uniform per CTA
    const int n0 = blockIdx.x * BN;
    const __half* __restrict__ Bmat =
        (MODE == 0) ? (g_w1h + (size_t)e * HD * FD) : (g_w2h + (size_t)e * FD * HD);
    const float* __restrict__ bias = (MODE == 0) ? (b1g + e * FD) : (b2g + e * HD);

    extern __shared__ __align__(128) char dsm[];
    __shared__ int rowP[BM];
    __shared__ const __half* rowSrc[BM];
    __shared__ float bias_s[BN];

    const int lane = tid & 31, warp = tid >> 5;
    const int wm = (warp & 1) * 64;            // 2x8 warp grid, 64x32 warp tile
    const int wn = (warp >> 1) * 32;
    const int grp = lane >> 2, quad = lane & 3;
    const uint32_t dsm32 = (uint32_t)__cvta_generic_to_shared(dsm);

    const __half* aSrc[2]; const __half* bSrc[4];
    uint32_t aOff[2], bOff[4];
    float acc[4][4][4];

    auto fillA = [&](int s) {
        const uint32_t base = dsm32 + s * STAGE_B;
#pragma unroll
        for (int i = 0; i < 2; ++i) cp16(base + aOff[i], aSrc[i]);
#pragma unroll
        for (int i = 0; i < 2; ++i) aSrc[i] += BK;
    };
    auto fillB = [&](int s) {                   // commits the group
        const uint32_t base = dsm32 + s * STAGE_B;
#pragma unroll
        for (int i = 0; i < 4; ++i) cp16(base + bOff[i], bSrc[i]);
        asm volatile("cp.async.commit_group;\n" ::: "memory");
#pragma unroll
        for (int i = 0; i < 4; ++i) bSrc[i] += (size_t)BK * N;
    };

    if (active) {
        if (tid < BM) {
            int gi = rowBase + tid;
            int pp = (gi < cnt) ? g_list[e][gi] : -1;
            rowP[tid] = pp;
            rowSrc[tid] = (MODE == 0)
                ? ((pp >= 0) ? g_xh + (size_t)(pp >> 1) * HD : g_xh)
                : ((pp >= 0) ? g_hh + (size_t)pp * FD : g_hh);
        }
        if (tid < BN) bias_s[tid] = bias[n0 + tid];
        __syncthreads();
#pragma unroll
        for (int i = 0; i < 2; ++i) {           // A: 1024 chunks / 512 thr
            int id = tid + i * GT;
            int ra = id >> 3, ca = id & 7;
            aSrc[i] = rowSrc[ra] + ca * 8;
            aOff[i] = (ra * AS + ca * 8) * 2;
        }
#pragma unroll
        for (int i = 0; i < 4; ++i) {           // B: 2048 chunks / 512 thr
            int id = tid + i * GT;
            int rb = id >> 5, cb = id & 31;
            bSrc[i] = Bmat + (size_t)rb * N + n0 + cb * 8;
            bOff[i] = A_BYTES + (rb * BS2 + cb * 8) * 2;
        }
#pragma unroll
        for (int a = 0; a < 4; a++)
#pragma unroll
            for (int b = 0; b < 4; b++)
#pragma unroll
                for (int c = 0; c < 4; c++) acc[a][b][c] = 0.f;
        fillA(0); fillB(0);                      // prefetch in flight during slices
        fillA(1); fillB(1);
    }

    if (MODE == 0) {                             // ---- overlapped prep slices ----
        const size_t cta = ((size_t)blockIdx.z * gridDim.y + blockIdx.y) * gridDim.x
                           + blockIdx.x;         // grid = 16 x 64 x 8 = 8192
        // zero out: 8192 CTAs x 256 float4 = 2.097M = NTOK*HD/4
        if (tid < 256)
            reinterpret_cast<float4*>(out)[cta * 256 + tid] =
                make_float4(0.f, 0.f, 0.f, 0.f);
        // convert w2: 8192 CTAs x 1024 float4 = 8.39M = NE*FD*HD/4
        uint2* dst = (uint2*)g_w2h;
#pragma unroll
        for (int k = 0; k < 2; ++k) {
            size_t i = cta * 1024 + k * GT + tid;
            dst[i] = cvt4(w2f[i]);
        }
    }
    if (!active) return;

    const int m = lane >> 3;
    const int row0 = wm + (lane & 15);
    for (int kt = 0; kt < KT; ++kt) {
        if (kt + 1 < KT) asm volatile("cp.async.wait_group 1;\n" ::: "memory");
        else             asm volatile("cp.async.wait_group 0;\n" ::: "memory");
        __syncthreads();                        // the ONLY barrier per kt
        const bool pf = kt + 2 < KT;
        const int ns = (kt + 2) % STAGES;
        const int s = kt % STAGES;
        const uint32_t aB = dsm32 + s * STAGE_B;
        const uint32_t bB = aB + A_BYTES;
#pragma unroll
        for (int ks = 0; ks < 4; ++ks) {        // four k16 steps per BK=64
            uint32_t af[4][4], bf[2][4];
#pragma unroll
            for (int np = 0; np < 2; ++np) {
                int kk = ks * 16 + (m & 1) * 8 + (lane & 7);
                int nn = wn + np * 16 + (m >> 1) * 8;
                ldsm_x4_t(bf[np], bB + (kk * BS2 + nn) * 2);
            }
            {
                const int col = ks * 16 + (lane >> 4) * 8;
                ldsm_x4(af[0], aB + (row0 * AS + col) * 2);
                ldsm_x4(af[1], aB + ((row0 + 16) * AS + col) * 2);
                mma_f16(acc[0][0], af[0], bf[0][0], bf[0][1]);
                mma_f16(acc[0][1], af[0], bf[0][2], bf[0][3]);
                mma_f16(acc[0][2], af[0], bf[1][0], bf[1][1]);
                mma_f16(acc[0][3], af[0], bf[1][2], bf[1][3]);
                ldsm_x4(af[2], aB + ((row0 + 32) * AS + col) * 2);
                mma_f16(acc[1][0], af[1], bf[0][0], bf[0][1]);
                mma_f16(acc[1][1], af[1], bf[0][2], bf[0][3]);
                mma_f16(acc[1][2], af[1], bf[1][0], bf[1][1]);
                mma_f16(acc[1][3], af[1], bf[1][2], bf[1][3]);
                ldsm_x4(af[3], aB + ((row0 + 48) * AS + col) * 2);
            }
            if (ks == 0 && pf) fillA(ns);        // spread the LDGSTS burst
            mma_f16(acc[2][0], af[2], bf[0][0], bf[0][1]);
            mma_f16(acc[2][1], af[2], bf[0][2], bf[0][3]);
            mma_f16(acc[2][2], af[2], bf[1][0], bf[1][1]);
            mma_f16(acc[2][3], af[2], bf[1][2], bf[1][3]);
            if (ks == 1 && pf) fillB(ns);
            mma_f16(acc[3][0], af[3], bf[0][0], bf[0][1]);
            mma_f16(acc[3][1], af[3], bf[0][2], bf[0][3]);
            mma_f16(acc[3][2], af[3], bf[1][0], bf[1][1]);
            mma_f16(acc[3][3], af[3], bf[1][2], bf[1][3]);
        }
    }
    __syncthreads();                            // stage buffers now reusable

    // ---------------- epilogue (smem-staged, coalesced global ops) ----------
    if (MODE == 0) {
        __half* stg = (__half*)dsm;             // [128][264] halves = 67.6 KB
#pragma unroll
        for (int mi = 0; mi < 4; ++mi)
#pragma unroll
            for (int half = 0; half < 2; ++half) {
                int li = wm + mi * 16 + grp + half * 8;
#pragma unroll
                for (int ni = 0; ni < 4; ++ni) {
                    int nc = wn + ni * 8 + 2 * quad;
                    float v0 = acc[mi][ni][half * 2 + 0] + bias_s[nc];
                    float v1 = acc[mi][ni][half * 2 + 1] + bias_s[nc + 1];
                    v0 = v0 / (1.f + __expf(-v0));        // silu
                    v1 = v1 / (1.f + __expf(-v1));
                    *reinterpret_cast<__half2*>(&stg[li * 264 + nc]) =
                        __floats2half2_rn(v0, v1);
                }
            }
        __syncthreads();
        for (int i = tid; i < BM * 32; i += GT) {    // 16B chunks, coalesced
            int r = i >> 5, ch = i & 31;
            int pp = rowP[r];
            if (pp < 0) continue;
            *reinterpret_cast<uint4*>(g_hh + (size_t)pp * FD + n0 + ch * 8) =
                *reinterpret_cast<uint4*>(&stg[r * 264 + ch * 8]);
        }
    } else {
        float* stg = (float*)dsm;               // [128][260] floats = 133 KB
#pragma unroll
        for (int mi = 0; mi < 4; ++mi)
#pragma unroll
            for (int half = 0; half < 2; ++half) {
                int li = wm + mi * 16 + grp + half * 8;
                int pp = rowP[li];
                float wgt = (pp >= 0) ? g_pairw[pp] : 0.f;
#pragma unroll
                for (int ni = 0; ni < 4; ++ni) {
                    int nc = wn + ni * 8 + 2 * quad;
                    stg[li * 260 + nc]     = (acc[mi][ni][half * 2 + 0] + bias_s[nc]) * wgt;
                    stg[li * 260 + nc + 1] = (acc[mi][ni][half * 2 + 1] + bias_s[nc + 1]) * wgt;
                }
            }
        __syncthreads();
        for (int i = tid; i < BM * 64; i += GT) {    // 16B-aligned v4 atomics
            int r = i >> 6, ch = i & 63;
            int pp = rowP[r];
            if (pp < 0) continue;
            float* orow = out + (size_t)(pp >> 1) * HD + n0 + ch * 4;
            const float* v = &stg[r * 260 + ch * 4];
            redv4(orow, v[0], v[1], v[2], v[3]);     // 2 commutative adds/elem
        }
    }
}

// ---------------- launch -----------------------------------------------------
extern "C" void kernel_launch(void* const* d_in, const int* in_sizes, int n_in,
                              void* d_out, int out_size) {
    const float* x  = (const float*)d_in[0];   // [4,2048,1024]
    const float* gw = (const float*)d_in[1];   // [8,1024]
    const float* w1 = (const float*)d_in[2];   // [8,1024,4096]
    const float* b1 = (const float*)d_in[3];   // [8,4096]
    const float* w2 = (const float*)d_in[4];   // [8,4096,1024]
    const float* b2 = (const float*)d_in[5];   // [8,1024]
    float* out = (float*)d_out;                // [4,2048,1024] fp32

    const int DSM = STAGE_B * STAGES;          // 156672 bytes (1 CTA/SM)
    cudaFuncSetAttribute(moe_gemm<0>, cudaFuncAttributeMaxDynamicSharedMemorySize, DSM);
    cudaFuncSetAttribute(moe_gemm<1>, cudaFuncAttributeMaxDynamicSharedMemorySize, DSM);

    // L1: zero counters (tiny, must precede gate atomics)
    zero_ctr<<<1, 32>>>();
    // L2: gating + x conversion + w1 conversion (one DRAM pass window)
    gate_kernel<<<NTOK, 256>>>(x, gw, (const float4*)w1);
    // L3: gemm1 — every CTA also zeroes an out-slice and converts a w2-slice
    moe_gemm<0><<<dim3(FD / BN, NTOK / BM, NE), GT, DSM>>>(
        b1, b2, (const float4*)w2, out);
    // L4: gemm2
    moe_gemm<1><<<dim3(HD / BN, NTOK / BM, NE), GT, DSM>>>(
        b1, b2, (const float4*)w2, out);
}

// round 17
// speedup vs baseline: 1.1113x; 1.1113x over previous
#include <cuda_runtime.h>
#include <cuda_fp16.h>
#include <cstdint>
#include <math.h>

// Problem dims (fixed by the dataset)
#define NTOK   8192            // B*S = 4*2048
#define HD     1024
#define FD     4096
#define NE     8
#define NPAIR  (NTOK * 2)      // top-2

// ---------------- scratch (__device__ globals: allocation-rule safe) --------
__device__ int    g_count[NE];
__device__ int    g_list[NE][NTOK];           // pair ids (t*2+k) per expert
__device__ float  g_pairw[NPAIR];             // gate prob per pair slot
__device__ __half g_w1h[(size_t)NE * HD * FD];   // 67 MB  [e][H][F]
__device__ __half g_w2h[(size_t)NE * FD * HD];   // 67 MB  [e][F][H]
__device__ __half g_xh[(size_t)NTOK * HD];       // 16 MB
__device__ __half g_hh[(size_t)NPAIR * FD];      // 134 MB fp16 intermediate

__device__ __forceinline__ uint2 cvt4(float4 v) {
    uint2 o;
    *reinterpret_cast<__half2*>(&o.x) = __floats2half2_rn(v.x, v.y);
    *reinterpret_cast<__half2*>(&o.y) = __floats2half2_rn(v.z, v.w);
    return o;
}

// ---------------- zero the expert counters (must precede gate atomics) ------
__global__ void zero_ctr() {
    if (threadIdx.x < NE) g_count[threadIdx.x] = 0;
}

// ---------------- gating + x fp16 convert + w1 convert (fused) --------------
__global__ void gate_kernel(const float* __restrict__ x,
                            const float* __restrict__ gw,
                            const float4* __restrict__ w1f) {
    const int t = blockIdx.x;
    const int warp = threadIdx.x >> 5, lane = threadIdx.x & 31;
    const int tid = threadIdx.x;
    __shared__ float logits[NE];
    const float* xr = x + (size_t)t * HD;
    {   // fused x -> fp16 (row is cache-hot)
        float4 v = *reinterpret_cast<const float4*>(xr + tid * 4);
        reinterpret_cast<uint2*>(g_xh + (size_t)t * HD)[tid] = cvt4(v);
    }
    {   // fused w1 -> fp16: 8192 blocks x 1024 float4 = full w1
        uint2* dst = (uint2*)g_w1h;
        const size_t base = (size_t)t * 1024 + tid;
#pragma unroll
        for (int k = 0; k < 4; ++k) dst[base + k * 256] = cvt4(w1f[base + k * 256]);
    }
    const float* wr = gw + warp * HD;       // 8 warps = 8 experts
    float s = 0.f;
#pragma unroll 8
    for (int h = lane; h < HD; h += 32) s = fmaf(xr[h], wr[h], s);
#pragma unroll
    for (int o = 16; o > 0; o >>= 1) s += __shfl_xor_sync(0xffffffffu, s, o);
    if (lane == 0) logits[warp] = s;
    __syncthreads();
    if (threadIdx.x == 0) {
        float mx = logits[0];
        for (int e = 1; e < NE; e++) mx = fmaxf(mx, logits[e]);
        float pe[NE]; float den = 0.f;
        for (int e = 0; e < NE; e++) { pe[e] = expf(logits[e] - mx); den += pe[e]; }
        int i1 = 0;
        for (int e = 1; e < NE; e++) if (pe[e] > pe[i1]) i1 = e;  // lowest idx on tie
        int i2 = (i1 == 0) ? 1 : 0;
        for (int e = 0; e < NE; e++) if (e != i1 && pe[e] > pe[i2]) i2 = e;
        float inv = 1.f / den;
        int p0 = t * 2, p1 = t * 2 + 1;
        g_pairw[p0] = pe[i1] * inv;
        g_pairw[p1] = pe[i2] * inv;
        int k0 = atomicAdd(&g_count[i1], 1); g_list[i1][k0] = p0;
        int k1 = atomicAdd(&g_count[i2], 1); g_list[i2][k1] = p1;
    }
}

// ---------------- mma / ldmatrix helpers ------------------------------------
__device__ __forceinline__ void mma_f16(float c[4], const uint32_t a[4],
                                        uint32_t b0, uint32_t b1) {
    asm volatile(
        "mma.sync.aligned.m16n8k16.row.col.f32.f16.f16.f32 "
        "{%0,%1,%2,%3},{%4,%5,%6,%7},{%8,%9},{%0,%1,%2,%3};\n"
        : "+f"(c[0]), "+f"(c[1]), "+f"(c[2]), "+f"(c[3])
        : "r"(a[0]), "r"(a[1]), "r"(a[2]), "r"(a[3]), "r"(b0), "r"(b1));
}
__device__ __forceinline__ void ldsm_x4(uint32_t r[4], uint32_t a) {
    asm volatile("ldmatrix.sync.aligned.m8n8.x4.shared.b16 {%0,%1,%2,%3},[%4];\n"
                 : "=r"(r[0]), "=r"(r[1]), "=r"(r[2]), "=r"(r[3]) : "r"(a));
}
__device__ __forceinline__ void ldsm_x4_t(uint32_t r[4], uint32_t a) {
    asm volatile("ldmatrix.sync.aligned.m8n8.x4.trans.shared.b16 {%0,%1,%2,%3},[%4];\n"
                 : "=r"(r[0]), "=r"(r[1]), "=r"(r[2]), "=r"(r[3]) : "r"(a));
}
__device__ __forceinline__ void cp16(uint32_t dst, const void* src) {
    asm volatile("cp.async.cg.shared.global [%0], [%1], 16;\n" :: "r"(dst), "l"(src));
}
__device__ __forceinline__ void redv4(float* a, float v0, float v1, float v2, float v3) {
    asm volatile("red.global.add.v4.f32 [%0], {%1,%2,%3,%4};"
                 :: "l"(a), "f"(v0), "f"(v1), "f"(v2), "f"(v3) : "memory");
}

// ---------------- grouped gather-GEMM (fp16 in, fp32 acc) -------------------
// CTA tile 128x128, 8 warps of 64x32 (2 CTAs/SM), BK=64, 3-stage pipeline.
// ldmatrix interleaved with MMA groups; stage fill split across ks steps.
#define BM 128
#define BN 128
#define BK 64
#define STAGES 3
#define AS 72                  // A row stride in halves (144B, 16B-aligned)
#define BS2 136                // B row stride in halves (272B, 16B-aligned)
#define A_BYTES (BM * AS * 2)              // 18432
#define STAGE_B (A_BYTES + BK * BS2 * 2)   // 35840

template <int MODE>
__global__ __launch_bounds__(256, 2)
void moe_gemm(const float* __restrict__ b1g, const float* __restrict__ b2g,
              const float4* __restrict__ w2f, float* __restrict__ out) {
    constexpr int K = (MODE == 0) ? HD : FD;
    constexpr int N = (MODE == 0) ? FD : HD;
    constexpr int KT = K / BK;
    const int tid = threadIdx.x;
    const int e = blockIdx.z;
    const int cnt = g_count[e];
    const int rowBase = blockIdx.y * BM;
    const bool active = rowBase < cnt;          // uniform per CTA
    const int n0 = blockIdx.x * BN;
    const __half* __restrict__ Bmat =
        (MODE == 0) ? (g_w1h + (size_t)e * HD * FD) : (g_w2h + (size_t)e * FD * HD);
    const float* __restrict__ bias = (MODE == 0) ? (b1g + e * FD) : (b2g + e * HD);

    extern __shared__ __align__(128) char dsm[];
    __shared__ int rowP[BM];
    __shared__ const __half* rowSrc[BM];
    __shared__ float bias_s[BN];

    const int lane = tid & 31, warp = tid >> 5;
    const int wm = (warp & 1) * 64;            // 2x4 warp grid, 64x32 warp tile
    const int wn = (warp >> 1) * 32;
    const int grp = lane >> 2, quad = lane & 3;
    const uint32_t dsm32 = (uint32_t)__cvta_generic_to_shared(dsm);

    const __half* aSrc[4]; const __half* bSrc[4];
    uint32_t aOff[4], bOff[4];
    float acc[4][4][4];

    auto fillA = [&](int s) {
        const uint32_t base = dsm32 + s * STAGE_B;
#pragma unroll
        for (int i = 0; i < 4; ++i) cp16(base + aOff[i], aSrc[i]);
#pragma unroll
        for (int i = 0; i < 4; ++i) aSrc[i] += BK;
    };
    auto fillB = [&](int s) {                   // commits the group
        const uint32_t base = dsm32 + s * STAGE_B;
#pragma unroll
        for (int i = 0; i < 4; ++i) cp16(base + bOff[i], bSrc[i]);
        asm volatile("cp.async.commit_group;\n" ::: "memory");
#pragma unroll
        for (int i = 0; i < 4; ++i) bSrc[i] += (size_t)BK * N;
    };

    if (active) {
        if (tid < BM) {
            int gi = rowBase + tid;
            int pp = (gi < cnt) ? g_list[e][gi] : -1;
            rowP[tid] = pp;
            rowSrc[tid] = (MODE == 0)
                ? ((pp >= 0) ? g_xh + (size_t)(pp >> 1) * HD : g_xh)
                : ((pp >= 0) ? g_hh + (size_t)pp * FD : g_hh);
            bias_s[tid] = bias[n0 + tid];          // BN==128
        }
        __syncthreads();
#pragma unroll
        for (int i = 0; i < 4; ++i) {
            int id = tid + i * 256;
            int ra = id >> 3, ca = id & 7;
            aSrc[i] = rowSrc[ra] + ca * 8;
            aOff[i] = (ra * AS + ca * 8) * 2;
            int rb = id >> 4, cb = id & 15;
            bSrc[i] = Bmat + (size_t)rb * N + n0 + cb * 8;
            bOff[i] = A_BYTES + (rb * BS2 + cb * 8) * 2;
        }
#pragma unroll
        for (int a = 0; a < 4; a++)
#pragma unroll
            for (int b = 0; b < 4; b++)
#pragma unroll
                for (int c = 0; c < 4; c++) acc[a][b][c] = 0.f;
        fillA(0); fillB(0);                      // prefetch in flight during slices
        fillA(1); fillB(1);
    }

    if (MODE == 0) {                             // ---- overlapped prep slices ----
        const size_t cta = ((size_t)blockIdx.z * gridDim.y + blockIdx.y) * gridDim.x
                           + blockIdx.x;         // grid = 32 x 64 x 8 = 16384
        if (tid < 128)
            reinterpret_cast<float4*>(out)[cta * 128 + tid] =
                make_float4(0.f, 0.f, 0.f, 0.f);
        uint2* dst = (uint2*)g_w2h;
#pragma unroll
        for (int k = 0; k < 2; ++k) {
            size_t i = cta * 512 + k * 256 + tid;
            dst[i] = cvt4(w2f[i]);
        }
    }
    if (!active) return;

    const int m = lane >> 3;
    const int row0 = wm + (lane & 15);
    for (int kt = 0; kt < KT; ++kt) {
        if (kt + 1 < KT) asm volatile("cp.async.wait_group 1;\n" ::: "memory");
        else             asm volatile("cp.async.wait_group 0;\n" ::: "memory");
        __syncthreads();                        // the ONLY barrier per kt
        const bool pf = kt + 2 < KT;
        const int ns = (kt + 2) % STAGES;
        const int s = kt % STAGES;
        const uint32_t aB = dsm32 + s * STAGE_B;
        const uint32_t bB = aB + A_BYTES;
#pragma unroll
        for (int ks = 0; ks < 4; ++ks) {        // four k16 steps per BK=64
            uint32_t af[4][4], bf[2][4];
            // B fragments + first two A fragments
#pragma unroll
            for (int np = 0; np < 2; ++np) {
                int kk = ks * 16 + (m & 1) * 8 + (lane & 7);
                int nn = wn + np * 16 + (m >> 1) * 8;
                ldsm_x4_t(bf[np], bB + (kk * BS2 + nn) * 2);
            }
            {
                const int col = ks * 16 + (lane >> 4) * 8;
                ldsm_x4(af[0], aB + (row0 * AS + col) * 2);
                ldsm_x4(af[1], aB + ((row0 + 16) * AS + col) * 2);
                // MMA group 0 overlaps af[2] fetch
                mma_f16(acc[0][0], af[0], bf[0][0], bf[0][1]);
                mma_f16(acc[0][1], af[0], bf[0][2], bf[0][3]);
                mma_f16(acc[0][2], af[0], bf[1][0], bf[1][1]);
                mma_f16(acc[0][3], af[0], bf[1][2], bf[1][3]);
                ldsm_x4(af[2], aB + ((row0 + 32) * AS + col) * 2);
                mma_f16(acc[1][0], af[1], bf[0][0], bf[0][1]);
                mma_f16(acc[1][1], af[1], bf[0][2], bf[0][3]);
                mma_f16(acc[1][2], af[1], bf[1][0], bf[1][1]);
                mma_f16(acc[1][3], af[1], bf[1][2], bf[1][3]);
                ldsm_x4(af[3], aB + ((row0 + 48) * AS + col) * 2);
            }
            if (ks == 0 && pf) fillA(ns);        // spread the LDGSTS burst
            mma_f16(acc[2][0], af[2], bf[0][0], bf[0][1]);
            mma_f16(acc[2][1], af[2], bf[0][2], bf[0][3]);
            mma_f16(acc[2][2], af[2], bf[1][0], bf[1][1]);
            mma_f16(acc[2][3], af[2], bf[1][2], bf[1][3]);
            if (ks == 1 && pf) fillB(ns);
            mma_f16(acc[3][0], af[3], bf[0][0], bf[0][1]);
            mma_f16(acc[3][1], af[3], bf[0][2], bf[0][3]);
            mma_f16(acc[3][2], af[3], bf[1][0], bf[1][1]);
            mma_f16(acc[3][3], af[3], bf[1][2], bf[1][3]);
        }
    }
    __syncthreads();                            // stage buffers now reusable

    // ---------------- epilogue (smem-staged, coalesced global ops) ----------
    if (MODE == 0) {
        __half* stg = (__half*)dsm;             // [128][136] halves
#pragma unroll
        for (int mi = 0; mi < 4; ++mi)
#pragma unroll
            for (int half = 0; half < 2; ++half) {
                int li = wm + mi * 16 + grp + half * 8;
#pragma unroll
                for (int ni = 0; ni < 4; ++ni) {
                    int nc = wn + ni * 8 + 2 * quad;
                    float v0 = acc[mi][ni][half * 2 + 0] + bias_s[nc];
                    float v1 = acc[mi][ni][half * 2 + 1] + bias_s[nc + 1];
                    v0 = v0 / (1.f + __expf(-v0));        // silu
                    v1 = v1 / (1.f + __expf(-v1));
                    *reinterpret_cast<__half2*>(&stg[li * 136 + nc]) =
                        __floats2half2_rn(v0, v1);
                }
            }
        __syncthreads();
        for (int i = tid; i < BM * 16; i += 256) {   // 16B chunks, coalesced
            int r = i >> 4, ch = i & 15;
            int pp = rowP[r];
            if (pp < 0) continue;
            *reinterpret_cast<uint4*>(g_hh + (size_t)pp * FD + n0 + ch * 8) =
                *reinterpret_cast<uint4*>(&stg[r * 136 + ch * 8]);
        }
    } else {
        float* stg = (float*)dsm;               // [128][132] floats
#pragma unroll
        for (int mi = 0; mi < 4; ++mi)
#pragma unroll
            for (int half = 0; half < 2; ++half) {
                int li = wm + mi * 16 + grp + half * 8;
                int pp = rowP[li];
                float wgt = (pp >= 0) ? g_pairw[pp] : 0.f;
#pragma unroll
                for (int ni = 0; ni < 4; ++ni) {
                    int nc = wn + ni * 8 + 2 * quad;
                    stg[li * 132 + nc]     = (acc[mi][ni][half * 2 + 0] + bias_s[nc]) * wgt;
                    stg[li * 132 + nc + 1] = (acc[mi][ni][half * 2 + 1] + bias_s[nc + 1]) * wgt;
                }
            }
        __syncthreads();
        for (int i = tid; i < BM * 32; i += 256) {   // 16B-aligned v4 atomics
            int r = i >> 5, ch = i & 31;
            int pp = rowP[r];
            if (pp < 0) continue;
            float* orow = out + (size_t)(pp >> 1) * HD + n0 + ch * 4;
            const float* v = &stg[r * 132 + ch * 4];
            redv4(orow, v[0], v[1], v[2], v[3]);     // 2 commutative adds/elem
        }
    }
}

// ---------------- launch -----------------------------------------------------
extern "C" void kernel_launch(void* const* d_in, const int* in_sizes, int n_in,
                              void* d_out, int out_size) {
    const float* x  = (const float*)d_in[0];   // [4,2048,1024]
    const float* gw = (const float*)d_in[1];   // [8,1024]
    const float* w1 = (const float*)d_in[2];   // [8,1024,4096]
    const float* b1 = (const float*)d_in[3];   // [8,4096]
    const float* w2 = (const float*)d_in[4];   // [8,4096,1024]
    const float* b2 = (const float*)d_in[5];   // [8,1024]
    float* out = (float*)d_out;                // [4,2048,1024] fp32

    const int DSM = STAGE_B * STAGES;          // 107520 bytes (2 CTAs = 210 KB)
    cudaFuncSetAttribute(moe_gemm<0>, cudaFuncAttributeMaxDynamicSharedMemorySize, DSM);
    cudaFuncSetAttribute(moe_gemm<1>, cudaFuncAttributeMaxDynamicSharedMemorySize, DSM);

    // L1: zero counters (tiny, must precede gate atomics)
    zero_ctr<<<1, 32>>>();
    // L2: gating + x conversion + w1 conversion (one DRAM pass window)
    gate_kernel<<<NTOK, 256>>>(x, gw, (const float4*)w1);
    // L3: gemm1 — every CTA also zeroes an out-slice and converts a w2-slice
    moe_gemm<0><<<dim3(FD / BN, NTOK / BM, NE), 256, DSM>>>(
        b1, b2, (const float4*)w2, out);
    // L4: gemm2
    moe_gemm<1><<<dim3(HD / BN, NTOK / BM, NE), 256, DSM>>>(
        b1, b2, (const float4*)w2, out);
}